// round 4
// baseline (speedup 1.0000x reference)
#include <cuda_runtime.h>

// Problem shape (fixed by the dataset)
static constexpr int B_ = 16;
static constexpr int N_ = 2048;
static constexpr int D_ = 64;
static constexpr int T_ = 64;   // square tile
#define SCALE_F 0.022097086912079608f   // 1/sqrt(2048)

// Scratch: E = masked exp(scores) [b][n][m], and 1/column-sums [b][m].
// __device__ globals (no runtime allocation, per harness rules).
__device__ float g_E[(size_t)B_ * N_ * N_];      // 268 MB
__device__ float g_rdenom[B_ * N_];

// Load a 64x64 fp32 tile (row stride D_=64 in gmem) into smem with +1 pad.
// 256 threads, 16 elems each: thread -> row r = tid/4, 16-col chunk c = (tid%4)*16.
__device__ __forceinline__ void load_tile64(const float* __restrict__ src,
                                            float dst[T_][D_ + 1], int tid)
{
    const int r = tid >> 2;
    const int c = (tid & 3) << 4;
    const float4* s = reinterpret_cast<const float4*>(src + (size_t)r * D_ + c);
    float4 v0 = s[0], v1 = s[1], v2 = s[2], v3 = s[3];
    float* d = &dst[r][c];
    d[ 0]=v0.x; d[ 1]=v0.y; d[ 2]=v0.z; d[ 3]=v0.w;
    d[ 4]=v1.x; d[ 5]=v1.y; d[ 6]=v1.z; d[ 7]=v1.w;
    d[ 8]=v2.x; d[ 9]=v2.y; d[10]=v2.z; d[11]=v2.w;
    d[12]=v3.x; d[13]=v3.y; d[14]=v3.z; d[15]=v3.w;
}

// ---------------------------------------------------------------------------
// Pass 1: for each (b, m-tile): E[b,n,m] = mask ? 0 : exp(q[n]·k[m] * scale)
//         over ALL n; write E; write g_rdenom[b,m] = 1 / sum_n E[b,n,m].
// One block owns a full column stripe -> column sums need no atomics.
// Mask is int32 on the wire (bool promoted by the harness).
// ---------------------------------------------------------------------------
__global__ void __launch_bounds__(256, 2) pass1_kernel(
    const float* __restrict__ q, const float* __restrict__ k,
    const int* __restrict__ mask)
{
    __shared__ float Ks[T_][D_ + 1];
    __shared__ float Qs[T_][D_ + 1];
    __shared__ float colred[16][T_];

    const int b  = blockIdx.y;
    const int m0 = blockIdx.x * T_;
    const int tx = threadIdx.x;   // 0..15 -> m sub-cols (4 each)
    const int ty = threadIdx.y;   // 0..15 -> n sub-rows (4 each)
    const int tid = ty * 16 + tx;

    load_tile64(k + ((size_t)b * N_ + m0) * D_, Ks, tid);

    float colacc[4] = {0.f, 0.f, 0.f, 0.f};

    for (int n0 = 0; n0 < N_; n0 += T_) {
        __syncthreads();  // Qs reuse (and first-iter Ks visibility)
        load_tile64(q + ((size_t)b * N_ + n0) * D_, Qs, tid);
        __syncthreads();

        float acc[4][4] = {};
        #pragma unroll 16
        for (int d = 0; d < D_; d++) {
            const float a0 = Qs[ty*4+0][d], a1 = Qs[ty*4+1][d],
                        a2 = Qs[ty*4+2][d], a3 = Qs[ty*4+3][d];
            const float b0 = Ks[tx*4+0][d], b1 = Ks[tx*4+1][d],
                        b2 = Ks[tx*4+2][d], b3 = Ks[tx*4+3][d];
            acc[0][0] += a0*b0; acc[0][1] += a0*b1; acc[0][2] += a0*b2; acc[0][3] += a0*b3;
            acc[1][0] += a1*b0; acc[1][1] += a1*b1; acc[1][2] += a1*b2; acc[1][3] += a1*b3;
            acc[2][0] += a2*b0; acc[2][1] += a2*b1; acc[2][2] += a2*b2; acc[2][3] += a2*b3;
            acc[3][0] += a3*b0; acc[3][1] += a3*b1; acc[3][2] += a3*b2; acc[3][3] += a3*b3;
        }

        #pragma unroll
        for (int i = 0; i < 4; i++) {
            const size_t row = ((size_t)b * N_ + (size_t)(n0 + ty*4 + i)) * N_
                               + (size_t)(m0 + tx*4);
            const int4 mk = *reinterpret_cast<const int4*>(mask + row);
            float4 e;
            e.x = mk.x ? 0.f : __expf(acc[i][0] * SCALE_F);
            e.y = mk.y ? 0.f : __expf(acc[i][1] * SCALE_F);
            e.z = mk.z ? 0.f : __expf(acc[i][2] * SCALE_F);
            e.w = mk.w ? 0.f : __expf(acc[i][3] * SCALE_F);
            *reinterpret_cast<float4*>(g_E + row) = e;
            colacc[0] += e.x; colacc[1] += e.y; colacc[2] += e.z; colacc[3] += e.w;
        }
    }

    #pragma unroll
    for (int j = 0; j < 4; j++) colred[ty][tx*4 + j] = colacc[j];
    __syncthreads();

    if (tid < T_) {
        float s = 0.f;
        #pragma unroll
        for (int r = 0; r < 16; r++) s += colred[r][tid];
        g_rdenom[b * N_ + m0 + tid] = 1.0f / s;
    }
}

// ---------------------------------------------------------------------------
// Pass 2: out[b, n, :] = sum_m E[b,n,m] * (v[b,m,:] * rdenom[b,m])
// ---------------------------------------------------------------------------
__global__ void __launch_bounds__(256, 2) pass2_kernel(
    const float* __restrict__ v, float* __restrict__ out)
{
    __shared__ float Es[T_][T_ + 1];   // [n][m]
    __shared__ float Vs[T_][D_ + 1];   // [m][d], pre-scaled by rdenom

    const int b  = blockIdx.y;
    const int n0 = blockIdx.x * T_;
    const int tx = threadIdx.x;   // d sub-cols
    const int ty = threadIdx.y;   // n sub-rows
    const int tid = ty * 16 + tx;

    float acc[4][4] = {};

    for (int m0 = 0; m0 < N_; m0 += T_) {
        __syncthreads();
        // E tile [64n x 64m]
        {
            const int r = tid >> 2;
            const int c = (tid & 3) << 4;
            const float4* s = reinterpret_cast<const float4*>(
                g_E + ((size_t)b * N_ + (size_t)(n0 + r)) * N_ + (size_t)(m0 + c));
            float4 v0 = s[0], v1 = s[1], v2 = s[2], v3 = s[3];
            float* d = &Es[r][c];
            d[ 0]=v0.x; d[ 1]=v0.y; d[ 2]=v0.z; d[ 3]=v0.w;
            d[ 4]=v1.x; d[ 5]=v1.y; d[ 6]=v1.z; d[ 7]=v1.w;
            d[ 8]=v2.x; d[ 9]=v2.y; d[10]=v2.z; d[11]=v2.w;
            d[12]=v3.x; d[13]=v3.y; d[14]=v3.z; d[15]=v3.w;
        }
        // V tile [64m x 64d], scaled by rdenom[m]
        {
            const int r = tid >> 2;
            const int c = (tid & 3) << 4;
            const float rd = g_rdenom[b * N_ + m0 + r];
            const float4* s = reinterpret_cast<const float4*>(
                v + ((size_t)b * N_ + (size_t)(m0 + r)) * D_ + c);
            float4 v0 = s[0], v1 = s[1], v2 = s[2], v3 = s[3];
            float* d = &Vs[r][c];
            d[ 0]=v0.x*rd; d[ 1]=v0.y*rd; d[ 2]=v0.z*rd; d[ 3]=v0.w*rd;
            d[ 4]=v1.x*rd; d[ 5]=v1.y*rd; d[ 6]=v1.z*rd; d[ 7]=v1.w*rd;
            d[ 8]=v2.x*rd; d[ 9]=v2.y*rd; d[10]=v2.z*rd; d[11]=v2.w*rd;
            d[12]=v3.x*rd; d[13]=v3.y*rd; d[14]=v3.z*rd; d[15]=v3.w*rd;
        }
        __syncthreads();

        #pragma unroll 16
        for (int m = 0; m < T_; m++) {
            const float a0 = Es[ty*4+0][m], a1 = Es[ty*4+1][m],
                        a2 = Es[ty*4+2][m], a3 = Es[ty*4+3][m];
            const float b0 = Vs[m][tx*4+0], b1 = Vs[m][tx*4+1],
                        b2 = Vs[m][tx*4+2], b3 = Vs[m][tx*4+3];
            acc[0][0] += a0*b0; acc[0][1] += a0*b1; acc[0][2] += a0*b2; acc[0][3] += a0*b3;
            acc[1][0] += a1*b0; acc[1][1] += a1*b1; acc[1][2] += a1*b2; acc[1][3] += a1*b3;
            acc[2][0] += a2*b0; acc[2][1] += a2*b1; acc[2][2] += a2*b2; acc[2][3] += a2*b3;
            acc[3][0] += a3*b0; acc[3][1] += a3*b1; acc[3][2] += a3*b2; acc[3][3] += a3*b3;
        }
    }

    #pragma unroll
    for (int i = 0; i < 4; i++) {
        float4 o = make_float4(acc[i][0], acc[i][1], acc[i][2], acc[i][3]);
        *reinterpret_cast<float4*>(
            out + ((size_t)b * N_ + (size_t)(n0 + ty*4 + i)) * D_ + (size_t)(tx*4)) = o;
    }
}

// ---------------------------------------------------------------------------
extern "C" void kernel_launch(void* const* d_in, const int* in_sizes, int n_in,
                              void* d_out, int out_size)
{
    const float* q = (const float*)d_in[0];
    const float* k = (const float*)d_in[1];
    const float* v = (const float*)d_in[2];
    const int*   mask = (const int*)d_in[3];
    float* out = (float*)d_out;

    dim3 grid(N_ / T_, B_);   // (32, 16)
    dim3 block(16, 16);
    pass1_kernel<<<grid, block>>>(q, k, mask);
    pass2_kernel<<<grid, block>>>(v, out);
}

// round 6
// speedup vs baseline: 3.7050x; 3.7050x over previous
#include <cuda_runtime.h>
#include <cuda_fp16.h>
#include <cstdint>

// ---------------------------------------------------------------------------
static constexpr int B_ = 16;
static constexpr int N_ = 2048;
static constexpr int D_ = 64;
static constexpr int NW = N_ / 32;        // 64 mask words per row
#define SCALE_F 0.022097086912079608f     // 1/sqrt(2048)

// Scratch (__device__ globals; no runtime allocation)
__device__ __half    g_Qh[(size_t)B_ * N_ * D_];   // 4 MB
__device__ __half    g_Kh[(size_t)B_ * N_ * D_];   // 4 MB
__device__ __half    g_Vs[(size_t)B_ * N_ * D_];   // 4 MB  V' = V * rd[m]
__device__ unsigned  g_mbN[(size_t)B_ * N_ * NW];  // mask bits, word over m
__device__ unsigned  g_mbT[(size_t)B_ * N_ * NW];  // mask bits, word over n
__device__ float     g_rd[B_ * N_];                // 1/colsum

// ---------------------------------------------------------------------------
__device__ __forceinline__ uint32_t smem_u32(const void* p) {
    uint32_t a;
    asm("{ .reg .u64 t; cvta.to.shared.u64 t, %1; cvt.u32.u64 %0, t; }" : "=r"(a) : "l"(p));
    return a;
}
__device__ __forceinline__ void ldsm_x4(uint32_t a[4], uint32_t addr) {
    asm volatile("ldmatrix.sync.aligned.m8n8.x4.shared.b16 {%0,%1,%2,%3}, [%4];"
        : "=r"(a[0]), "=r"(a[1]), "=r"(a[2]), "=r"(a[3]) : "r"(addr));
}
__device__ __forceinline__ void ldsm_x2(uint32_t b[2], uint32_t addr) {
    asm volatile("ldmatrix.sync.aligned.m8n8.x2.shared.b16 {%0,%1}, [%2];"
        : "=r"(b[0]), "=r"(b[1]) : "r"(addr));
}
__device__ __forceinline__ void ldsm_x2t(uint32_t b[2], uint32_t addr) {
    asm volatile("ldmatrix.sync.aligned.m8n8.x2.trans.shared.b16 {%0,%1}, [%2];"
        : "=r"(b[0]), "=r"(b[1]) : "r"(addr));
}
__device__ __forceinline__ void mma16816(float c[4], const uint32_t a[4], const uint32_t b[2]) {
    asm volatile(
        "mma.sync.aligned.m16n8k16.row.col.f32.f16.f16.f32 "
        "{%0,%1,%2,%3}, {%4,%5,%6,%7}, {%8,%9}, {%0,%1,%2,%3};"
        : "+f"(c[0]), "+f"(c[1]), "+f"(c[2]), "+f"(c[3])
        : "r"(a[0]), "r"(a[1]), "r"(a[2]), "r"(a[3]), "r"(b[0]), "r"(b[1]));
}
__device__ __forceinline__ uint32_t h2u(__half2 h) { return *reinterpret_cast<uint32_t*>(&h); }

// ---------------------------------------------------------------------------
// Prep 1: pack the int32 mask into bitmasks in BOTH orientations, one read.
// Each warp handles a 32x32 tile: ballot gives the row-major word; per-lane
// bit extraction across the 32 ballots builds the transposed word.
__global__ void pack_mask_kernel(const int* __restrict__ mask) {
    const int warp = blockIdx.x * 8 + (threadIdx.x >> 5);
    const int lane = threadIdx.x & 31;
    const int m_t = warp & 63, n_t = (warp >> 6) & 63, b = warp >> 12;
    const int* src = mask + ((size_t)b * N_ + n_t * 32) * N_ + m_t * 32 + lane;
    unsigned* rowdst = g_mbN + ((size_t)b * N_ + n_t * 32) * NW + m_t;
    unsigned tw = 0;
    #pragma unroll
    for (int i = 0; i < 32; i++) {
        unsigned bal = __ballot_sync(0xffffffffu, src[(size_t)i * N_] != 0);
        if (lane == 0) rowdst[(size_t)i * NW] = bal;
        tw |= ((bal >> lane) & 1u) << i;
    }
    g_mbT[((size_t)b * N_ + m_t * 32 + lane) * NW + n_t] = tw;
}

// Prep 2: q,k -> fp16
__global__ void convert_qk_kernel(const float* __restrict__ q, const float* __restrict__ k) {
    size_t i = (size_t)blockIdx.x * 256 + threadIdx.x;
    g_Qh[i] = __float2half_rn(q[i]);
    g_Kh[i] = __float2half_rn(k[i]);
}

// Prep 3 (after colsum): V' = V * rd[m], fp16
__global__ void scale_v_kernel(const float* __restrict__ v) {
    size_t i = (size_t)blockIdx.x * 256 + threadIdx.x;
    int m = (int)((i / D_) % N_);
    int b = (int)(i / ((size_t)N_ * D_));
    g_Vs[i] = __float2half_rn(v[i] * g_rd[b * N_ + m]);
}

// ---------------------------------------------------------------------------
// Colsum: per (b, 128 m-rows) block: S^T = K·Q^T via HMMA, masked exp,
// per-lane row sums over all n, quad shfl-reduce, write rd = 1/sum.
__global__ void __launch_bounds__(256, 2) colsum_kernel() {
    __shared__ __half Kst[128 * 72];
    __shared__ __half Qs[64 * 72];
    const int tid = threadIdx.x, w = tid >> 5, lane = tid & 31;
    const int b = blockIdx.y, m0 = blockIdx.x * 128;

    const __half* Kg = g_Kh + ((size_t)b * N_ + m0) * D_;
    for (int i = tid; i < 128 * 8; i += 256) {
        int r = i >> 3, j = i & 7;
        *(int4*)&Kst[r * 72 + j * 8] = ((const int4*)Kg)[i];
    }
    __syncthreads();

    uint32_t Af[4][4];   // A = K rows (m), 4 k16 steps over D=64
    {
        int mat = lane >> 3;
        int row = w * 16 + (mat & 1) * 8 + (lane & 7);
        int colb = (mat >> 1) * 8;
        #pragma unroll
        for (int ks = 0; ks < 4; ks++)
            ldsm_x4(Af[ks], smem_u32(&Kst[row * 72 + ks * 16 + colb]));
    }

    const int mr0 = m0 + w * 16 + (lane >> 2);
    const unsigned* mT0 = g_mbT + ((size_t)b * N_ + mr0) * NW;       // row m
    const unsigned* mT1 = mT0 + 8 * NW;                              // row m+8
    float acc0 = 0.f, acc1 = 0.f;

    for (int n0 = 0; n0 < N_; n0 += 64) {
        __syncthreads();
        const __half* Qg = g_Qh + ((size_t)b * N_ + n0) * D_;
        for (int i = tid; i < 64 * 8; i += 256) {
            int r = i >> 3, j = i & 7;
            *(int4*)&Qs[r * 72 + j * 8] = ((const int4*)Qg)[i];
        }
        __syncthreads();

        const unsigned w00 = mT0[n0 / 32], w01 = mT0[n0 / 32 + 1];
        const unsigned w10 = mT1[n0 / 32], w11 = mT1[n0 / 32 + 1];
        const int brow = (lane & 7);
        const int bcb  = ((lane >> 3) & 1) * 8;

        #pragma unroll
        for (int j = 0; j < 8; j++) {
            float c[4] = {0.f, 0.f, 0.f, 0.f};
            #pragma unroll
            for (int ks = 0; ks < 4; ks++) {
                uint32_t Bf[2];
                ldsm_x2(Bf, smem_u32(&Qs[(j * 8 + brow) * 72 + ks * 16 + bcb]));
                mma16816(c, Af[ks], Bf);
            }
            const unsigned wa = (j < 4) ? w00 : w01;
            const unsigned wb = (j < 4) ? w10 : w11;
            const int sh = (j * 8 + (lane & 3) * 2) & 31;
            if (!((wa >> sh) & 1))       acc0 += __expf(c[0] * SCALE_F);
            if (!((wa >> (sh + 1)) & 1)) acc0 += __expf(c[1] * SCALE_F);
            if (!((wb >> sh) & 1))       acc1 += __expf(c[2] * SCALE_F);
            if (!((wb >> (sh + 1)) & 1)) acc1 += __expf(c[3] * SCALE_F);
        }
    }
    acc0 += __shfl_xor_sync(0xffffffffu, acc0, 1);
    acc0 += __shfl_xor_sync(0xffffffffu, acc0, 2);
    acc1 += __shfl_xor_sync(0xffffffffu, acc1, 1);
    acc1 += __shfl_xor_sync(0xffffffffu, acc1, 2);
    if ((lane & 3) == 0) {
        g_rd[b * N_ + mr0]     = 1.0f / acc0;
        g_rd[b * N_ + mr0 + 8] = 1.0f / acc1;
    }
}

// ---------------------------------------------------------------------------
// Out: per (b, 128 n-rows): loop m chunks of 64:
//   S = Q·K^T (HMMA) -> masked exp -> pack half2 as A-frags -> out += E'·V'
__global__ void __launch_bounds__(256, 2) out_kernel(float* __restrict__ out) {
    __shared__ __half Qst[128 * 72];
    __shared__ __half Ks[64 * 72];
    __shared__ __half Vsh[64 * 72];
    const int tid = threadIdx.x, w = tid >> 5, lane = tid & 31;
    const int b = blockIdx.y, n0 = blockIdx.x * 128;

    const __half* Qg = g_Qh + ((size_t)b * N_ + n0) * D_;
    for (int i = tid; i < 128 * 8; i += 256) {
        int r = i >> 3, j = i & 7;
        *(int4*)&Qst[r * 72 + j * 8] = ((const int4*)Qg)[i];
    }
    __syncthreads();

    uint32_t Qa[4][4];
    {
        int mat = lane >> 3;
        int row = w * 16 + (mat & 1) * 8 + (lane & 7);
        int colb = (mat >> 1) * 8;
        #pragma unroll
        for (int ks = 0; ks < 4; ks++)
            ldsm_x4(Qa[ks], smem_u32(&Qst[row * 72 + ks * 16 + colb]));
    }

    float o[8][4];
    #pragma unroll
    for (int dt = 0; dt < 8; dt++)
        #pragma unroll
        for (int e = 0; e < 4; e++) o[dt][e] = 0.f;

    const int nr0 = n0 + w * 16 + (lane >> 2);
    const unsigned* mN0 = g_mbN + ((size_t)b * N_ + nr0) * NW;   // row n
    const unsigned* mN1 = mN0 + 8 * NW;                          // row n+8

    for (int m0c = 0; m0c < N_; m0c += 64) {
        __syncthreads();
        const __half* Kg = g_Kh + ((size_t)b * N_ + m0c) * D_;
        const __half* Vg = g_Vs + ((size_t)b * N_ + m0c) * D_;
        for (int i = tid; i < 64 * 8; i += 256) {
            int r = i >> 3, j = i & 7;
            *(int4*)&Ks[r * 72 + j * 8]  = ((const int4*)Kg)[i];
            *(int4*)&Vsh[r * 72 + j * 8] = ((const int4*)Vg)[i];
        }
        __syncthreads();

        const unsigned w00 = mN0[m0c / 32], w01 = mN0[m0c / 32 + 1];
        const unsigned w10 = mN1[m0c / 32], w11 = mN1[m0c / 32 + 1];
        const int brow = (lane & 7);
        const int bcb  = ((lane >> 3) & 1) * 8;

        uint32_t Ae[4];
        #pragma unroll
        for (int j = 0; j < 8; j++) {
            float c[4] = {0.f, 0.f, 0.f, 0.f};
            #pragma unroll
            for (int ks = 0; ks < 4; ks++) {
                uint32_t Bf[2];
                ldsm_x2(Bf, smem_u32(&Ks[(j * 8 + brow) * 72 + ks * 16 + bcb]));
                mma16816(c, Qa[ks], Bf);
            }
            const unsigned wa = (j < 4) ? w00 : w01;
            const unsigned wb = (j < 4) ? w10 : w11;
            const int sh = (j * 8 + (lane & 3) * 2) & 31;
            float e0 = ((wa >> sh) & 1)       ? 0.f : __expf(c[0] * SCALE_F);
            float e1 = ((wa >> (sh + 1)) & 1) ? 0.f : __expf(c[1] * SCALE_F);
            float e2 = ((wb >> sh) & 1)       ? 0.f : __expf(c[2] * SCALE_F);
            float e3 = ((wb >> (sh + 1)) & 1) ? 0.f : __expf(c[3] * SCALE_F);
            if ((j & 1) == 0) {
                Ae[0] = h2u(__floats2half2_rn(e0, e1));
                Ae[1] = h2u(__floats2half2_rn(e2, e3));
            } else {
                Ae[2] = h2u(__floats2half2_rn(e0, e1));
                Ae[3] = h2u(__floats2half2_rn(e2, e3));
                const int vrow = (j >> 1) * 16 + (lane & 15);
                #pragma unroll
                for (int dt = 0; dt < 8; dt++) {
                    uint32_t Bv[2];
                    ldsm_x2t(Bv, smem_u32(&Vsh[vrow * 72 + dt * 8]));
                    mma16816(o[dt], Ae, Bv);
                }
            }
        }
    }

    float* obase = out + ((size_t)b * N_ + nr0) * D_;
    const int col0 = (lane & 3) * 2;
    #pragma unroll
    for (int dt = 0; dt < 8; dt++) {
        *(float2*)&obase[dt * 8 + col0]          = make_float2(o[dt][0], o[dt][1]);
        *(float2*)&obase[8 * D_ + dt * 8 + col0] = make_float2(o[dt][2], o[dt][3]);
    }
}

// ---------------------------------------------------------------------------
extern "C" void kernel_launch(void* const* d_in, const int* in_sizes, int n_in,
                              void* d_out, int out_size)
{
    const float* q = (const float*)d_in[0];
    const float* k = (const float*)d_in[1];
    const float* v = (const float*)d_in[2];
    const int* mask = (const int*)d_in[3];
    float* out = (float*)d_out;

    pack_mask_kernel<<<(B_ * 64 * 64) / 8, 256>>>(mask);
    convert_qk_kernel<<<(unsigned)(((size_t)B_ * N_ * D_) / 256), 256>>>(q, k);
    colsum_kernel<<<dim3(N_ / 128, B_), 256>>>();
    scale_v_kernel<<<(unsigned)(((size_t)B_ * N_ * D_) / 256), 256>>>(v);
    out_kernel<<<dim3(N_ / 128, B_), 256>>>(out);
}

// round 7
// speedup vs baseline: 4.3118x; 1.1638x over previous
#include <cuda_runtime.h>
#include <cuda_fp16.h>
#include <cstdint>

// ---------------------------------------------------------------------------
static constexpr int B_ = 16;
static constexpr int N_ = 2048;
static constexpr int D_ = 64;
static constexpr int NW = N_ / 32;        // 64 mask words per row
#define SCALE_F 0.022097086912079608f     // 1/sqrt(2048)

// Scratch (__device__ globals; no runtime allocation)
__device__ __half    g_Qh[(size_t)B_ * N_ * D_];   // 4 MB
__device__ __half    g_Kh[(size_t)B_ * N_ * D_];   // 4 MB
__device__ __half    g_Vs[(size_t)B_ * N_ * D_];   // 4 MB  V' = V * rd[m]
__device__ unsigned  g_mbN[(size_t)B_ * N_ * NW];  // mask bits, word over m
__device__ unsigned  g_mbT[(size_t)B_ * N_ * NW];  // mask bits, word over n

// ---------------------------------------------------------------------------
__device__ __forceinline__ uint32_t smem_u32(const void* p) {
    uint32_t a;
    asm("{ .reg .u64 t; cvta.to.shared.u64 t, %1; cvt.u32.u64 %0, t; }" : "=r"(a) : "l"(p));
    return a;
}
__device__ __forceinline__ void ldsm_x4(uint32_t a[4], uint32_t addr) {
    asm volatile("ldmatrix.sync.aligned.m8n8.x4.shared.b16 {%0,%1,%2,%3}, [%4];"
        : "=r"(a[0]), "=r"(a[1]), "=r"(a[2]), "=r"(a[3]) : "r"(addr));
}
__device__ __forceinline__ void ldsm_x4t(uint32_t a[4], uint32_t addr) {
    asm volatile("ldmatrix.sync.aligned.m8n8.x4.trans.shared.b16 {%0,%1,%2,%3}, [%4];"
        : "=r"(a[0]), "=r"(a[1]), "=r"(a[2]), "=r"(a[3]) : "r"(addr));
}
__device__ __forceinline__ void mma16816(float c[4], const uint32_t a[4], const uint32_t b[2]) {
    asm volatile(
        "mma.sync.aligned.m16n8k16.row.col.f32.f16.f16.f32 "
        "{%0,%1,%2,%3}, {%4,%5,%6,%7}, {%8,%9}, {%0,%1,%2,%3};"
        : "+f"(c[0]), "+f"(c[1]), "+f"(c[2]), "+f"(c[3])
        : "r"(a[0]), "r"(a[1]), "r"(a[2]), "r"(a[3]), "r"(b[0]), "r"(b[1]));
}
__device__ __forceinline__ uint32_t h2u(__half2 h) { return *reinterpret_cast<uint32_t*>(&h); }
__device__ __forceinline__ void cp16(uint32_t dst, const void* src) {
    asm volatile("cp.async.cg.shared.global [%0], [%1], 16;" :: "r"(dst), "l"(src));
}
__device__ __forceinline__ void cp_commit() { asm volatile("cp.async.commit_group;" ::: "memory"); }
__device__ __forceinline__ void cp_wait0()  { asm volatile("cp.async.wait_group 0;"  ::: "memory"); }

// ---------------------------------------------------------------------------
// Prep 1: pack int32 mask into bitmasks in BOTH orientations, one read.
__global__ void pack_mask_kernel(const int* __restrict__ mask) {
    const int warp = blockIdx.x * 8 + (threadIdx.x >> 5);
    const int lane = threadIdx.x & 31;
    const int m_t = warp & 63, n_t = (warp >> 6) & 63, b = warp >> 12;
    const int* src = mask + ((size_t)b * N_ + n_t * 32) * N_ + m_t * 32 + lane;
    unsigned* rowdst = g_mbN + ((size_t)b * N_ + n_t * 32) * NW + m_t;
    unsigned tw = 0;
    #pragma unroll
    for (int i = 0; i < 32; i++) {
        unsigned bal = __ballot_sync(0xffffffffu, src[(size_t)i * N_] != 0);
        if (lane == 0) rowdst[(size_t)i * NW] = bal;
        tw |= ((bal >> lane) & 1u) << i;
    }
    g_mbT[((size_t)b * N_ + m_t * 32 + lane) * NW + n_t] = tw;
}

// Prep 2: q,k -> fp16
__global__ void convert_qk_kernel(const float* __restrict__ q, const float* __restrict__ k) {
    size_t i = (size_t)blockIdx.x * 256 + threadIdx.x;
    g_Qh[i] = __float2half_rn(q[i]);
    g_Kh[i] = __float2half_rn(k[i]);
}

// ---------------------------------------------------------------------------
// Colsum: per (b, 128 m-rows): S^T = K·Q^T via HMMA over all n, masked exp,
// per-lane sums, quad-reduce -> rd; then scale V rows in-block (V' = V*rd).
__global__ void __launch_bounds__(256, 2) colsum_kernel(const float* __restrict__ v) {
    __shared__ __half Kst[128 * 72];
    __shared__ __half Qs[2][64 * 72];
    __shared__ float rdsm[128];
    const int tid = threadIdx.x, w = tid >> 5, lane = tid & 31;
    const int b = blockIdx.y, m0 = blockIdx.x * 128;

    // prefetch Q chunk 0 (async)
    {
        const int4* Qg = (const int4*)(g_Qh + (size_t)b * N_ * D_);
        #pragma unroll 2
        for (int i = tid; i < 512; i += 256) {
            int r = i >> 3, j = i & 7;
            cp16(smem_u32(&Qs[0][r * 72 + j * 8]), Qg + i);
        }
        cp_commit();
    }
    // K tile (plain loads)
    {
        const int4* Kg = (const int4*)(g_Kh + ((size_t)b * N_ + m0) * D_);
        #pragma unroll 4
        for (int i = tid; i < 1024; i += 256) {
            int r = i >> 3, j = i & 7;
            *(int4*)&Kst[r * 72 + j * 8] = Kg[i];
        }
    }
    cp_wait0();
    __syncthreads();

    uint32_t Af[4][4];   // A = K rows (m), 4 k16 steps over D=64
    {
        int mat = lane >> 3;
        int row = w * 16 + (mat & 1) * 8 + (lane & 7);
        int colb = (mat >> 1) * 8;
        #pragma unroll
        for (int ks = 0; ks < 4; ks++)
            ldsm_x4(Af[ks], smem_u32(&Kst[row * 72 + ks * 16 + colb]));
    }

    const int mr0 = m0 + w * 16 + (lane >> 2);
    const unsigned* mT0 = g_mbT + ((size_t)b * N_ + mr0) * NW;
    const unsigned* mT1 = mT0 + 8 * NW;
    float acc0 = 0.f, acc1 = 0.f;

    const int r4  = (lane >> 4) * 8 + (lane & 7);       // row within 16-row pair
    const int c4  = ((lane >> 3) & 1) * 8;              // 8-col half select
    const int sh0 = (lane & 3) * 2;

    for (int c = 0; c < 32; c++) {
        const int n0 = c * 64;
        if (c + 1 < 32) {   // prefetch next chunk
            const int4* Qg = (const int4*)(g_Qh + ((size_t)b * N_ + n0 + 64) * D_);
            #pragma unroll 2
            for (int i = tid; i < 512; i += 256) {
                int r = i >> 3, j = i & 7;
                cp16(smem_u32(&Qs[(c + 1) & 1][r * 72 + j * 8]), Qg + i);
            }
        }
        cp_commit();

        const __half* Qb = Qs[c & 1];
        const unsigned w00 = mT0[c * 2], w01 = mT0[c * 2 + 1];
        const unsigned w10 = mT1[c * 2], w11 = mT1[c * 2 + 1];

        #pragma unroll
        for (int j2 = 0; j2 < 4; j2++) {
            float c0[4] = {0.f, 0.f, 0.f, 0.f}, c1[4] = {0.f, 0.f, 0.f, 0.f};
            #pragma unroll
            for (int ks = 0; ks < 4; ks++) {
                uint32_t B4[4];
                ldsm_x4(B4, smem_u32(&Qb[(j2 * 16 + r4) * 72 + ks * 16 + c4]));
                mma16816(c0, Af[ks], B4);
                mma16816(c1, Af[ks], B4 + 2);
            }
            const unsigned wa = (j2 < 2) ? w00 : w01;
            const unsigned wb = (j2 < 2) ? w10 : w11;
            {   // j = 2*j2
                const int sh = (j2 * 16 + sh0) & 31;
                if (!((wa >> sh) & 1))       acc0 += __expf(c0[0] * SCALE_F);
                if (!((wa >> (sh + 1)) & 1)) acc0 += __expf(c0[1] * SCALE_F);
                if (!((wb >> sh) & 1))       acc1 += __expf(c0[2] * SCALE_F);
                if (!((wb >> (sh + 1)) & 1)) acc1 += __expf(c0[3] * SCALE_F);
            }
            {   // j = 2*j2+1
                const int sh = (j2 * 16 + 8 + sh0) & 31;
                if (!((wa >> sh) & 1))       acc0 += __expf(c1[0] * SCALE_F);
                if (!((wa >> (sh + 1)) & 1)) acc0 += __expf(c1[1] * SCALE_F);
                if (!((wb >> sh) & 1))       acc1 += __expf(c1[2] * SCALE_F);
                if (!((wb >> (sh + 1)) & 1)) acc1 += __expf(c1[3] * SCALE_F);
            }
        }
        cp_wait0();
        __syncthreads();
    }

    acc0 += __shfl_xor_sync(0xffffffffu, acc0, 1);
    acc0 += __shfl_xor_sync(0xffffffffu, acc0, 2);
    acc1 += __shfl_xor_sync(0xffffffffu, acc1, 1);
    acc1 += __shfl_xor_sync(0xffffffffu, acc1, 2);
    if ((lane & 3) == 0) {
        rdsm[w * 16 + (lane >> 2)]     = 1.0f / acc0;
        rdsm[w * 16 + (lane >> 2) + 8] = 1.0f / acc1;
    }
    __syncthreads();

    // Fused: V' = V * rd for this block's 128 m-rows
    {
        const float2* Vg = (const float2*)(v + ((size_t)b * N_ + m0) * D_);
        __half2* Vd = (__half2*)(g_Vs + ((size_t)b * N_ + m0) * D_);
        #pragma unroll 4
        for (int i = tid; i < 128 * 32; i += 256) {
            const float rd = rdsm[i >> 5];
            float2 f = Vg[i];
            Vd[i] = __floats2half2_rn(f.x * rd, f.y * rd);
        }
    }
}

// ---------------------------------------------------------------------------
// Out: per (b, 128 n-rows): loop m chunks of 64 (double-buffered):
//   S = Q·K^T (HMMA) -> masked exp -> half2 A-frags -> out += E'·V'
__global__ void __launch_bounds__(256, 2) out_kernel(float* __restrict__ out) {
    extern __shared__ __half dsm[];
    __half* Qst = dsm;                 // 128*72
    __half* Ksb = dsm + 128 * 72;      // 2 x 64*72
    __half* Vsb = Ksb + 2 * 64 * 72;   // 2 x 64*72
    const int tid = threadIdx.x, w = tid >> 5, lane = tid & 31;
    const int b = blockIdx.y, n0 = blockIdx.x * 128;

    // prefetch K/V chunk 0
    {
        const int4* Kg = (const int4*)(g_Kh + (size_t)b * N_ * D_);
        const int4* Vg = (const int4*)(g_Vs + (size_t)b * N_ * D_);
        #pragma unroll 2
        for (int i = tid; i < 512; i += 256) {
            int r = i >> 3, j = i & 7;
            cp16(smem_u32(&Ksb[r * 72 + j * 8]), Kg + i);
            cp16(smem_u32(&Vsb[r * 72 + j * 8]), Vg + i);
        }
        cp_commit();
    }
    // Q tile (plain)
    {
        const int4* Qg = (const int4*)(g_Qh + ((size_t)b * N_ + n0) * D_);
        #pragma unroll 4
        for (int i = tid; i < 1024; i += 256) {
            int r = i >> 3, j = i & 7;
            *(int4*)&Qst[r * 72 + j * 8] = Qg[i];
        }
    }
    cp_wait0();
    __syncthreads();

    uint32_t Qa[4][4];
    {
        int mat = lane >> 3;
        int row = w * 16 + (mat & 1) * 8 + (lane & 7);
        int colb = (mat >> 1) * 8;
        #pragma unroll
        for (int ks = 0; ks < 4; ks++)
            ldsm_x4(Qa[ks], smem_u32(&Qst[row * 72 + ks * 16 + colb]));
    }

    float o[8][4];
    #pragma unroll
    for (int dt = 0; dt < 8; dt++)
        #pragma unroll
        for (int e = 0; e < 4; e++) o[dt][e] = 0.f;

    const int nr0 = n0 + w * 16 + (lane >> 2);
    const unsigned* mN0 = g_mbN + ((size_t)b * N_ + nr0) * NW;
    const unsigned* mN1 = mN0 + 8 * NW;

    const int r4  = (lane >> 4) * 8 + (lane & 7);
    const int c4  = ((lane >> 3) & 1) * 8;
    const int sh0 = (lane & 3) * 2;
    const int vr  = lane & 15;
    const int vco = (lane >> 4) * 8;

    for (int c = 0; c < 32; c++) {
        if (c + 1 < 32) {   // prefetch next K/V chunk
            const int4* Kg = (const int4*)(g_Kh + ((size_t)b * N_ + (c + 1) * 64) * D_);
            const int4* Vg = (const int4*)(g_Vs + ((size_t)b * N_ + (c + 1) * 64) * D_);
            const int buf = ((c + 1) & 1) * 64 * 72;
            #pragma unroll 2
            for (int i = tid; i < 512; i += 256) {
                int r = i >> 3, j = i & 7;
                cp16(smem_u32(&Ksb[buf + r * 72 + j * 8]), Kg + i);
                cp16(smem_u32(&Vsb[buf + r * 72 + j * 8]), Vg + i);
            }
        }
        cp_commit();

        const __half* Kb = Ksb + (c & 1) * 64 * 72;
        const __half* Vb = Vsb + (c & 1) * 64 * 72;
        const unsigned w00 = mN0[c * 2], w01 = mN0[c * 2 + 1];
        const unsigned w10 = mN1[c * 2], w11 = mN1[c * 2 + 1];

        #pragma unroll
        for (int j2 = 0; j2 < 4; j2++) {
            float c0[4] = {0.f, 0.f, 0.f, 0.f}, c1[4] = {0.f, 0.f, 0.f, 0.f};
            #pragma unroll
            for (int ks = 0; ks < 4; ks++) {
                uint32_t B4[4];
                ldsm_x4(B4, smem_u32(&Kb[(j2 * 16 + r4) * 72 + ks * 16 + c4]));
                mma16816(c0, Qa[ks], B4);
                mma16816(c1, Qa[ks], B4 + 2);
            }
            const unsigned wa = (j2 < 2) ? w00 : w01;
            const unsigned wb = (j2 < 2) ? w10 : w11;
            uint32_t Ae[4];
            {   // j = 2*j2 -> k rows 0-7 of A fragment
                const int sh = (j2 * 16 + sh0) & 31;
                float e0 = ((wa >> sh) & 1)       ? 0.f : __expf(c0[0] * SCALE_F);
                float e1 = ((wa >> (sh + 1)) & 1) ? 0.f : __expf(c0[1] * SCALE_F);
                float e2 = ((wb >> sh) & 1)       ? 0.f : __expf(c0[2] * SCALE_F);
                float e3 = ((wb >> (sh + 1)) & 1) ? 0.f : __expf(c0[3] * SCALE_F);
                Ae[0] = h2u(__floats2half2_rn(e0, e1));
                Ae[1] = h2u(__floats2half2_rn(e2, e3));
            }
            {   // j = 2*j2+1 -> k rows 8-15
                const int sh = (j2 * 16 + 8 + sh0) & 31;
                float e0 = ((wa >> sh) & 1)       ? 0.f : __expf(c1[0] * SCALE_F);
                float e1 = ((wa >> (sh + 1)) & 1) ? 0.f : __expf(c1[1] * SCALE_F);
                float e2 = ((wb >> sh) & 1)       ? 0.f : __expf(c1[2] * SCALE_F);
                float e3 = ((wb >> (sh + 1)) & 1) ? 0.f : __expf(c1[3] * SCALE_F);
                Ae[2] = h2u(__floats2half2_rn(e0, e1));
                Ae[3] = h2u(__floats2half2_rn(e2, e3));
            }
            #pragma unroll
            for (int dt2 = 0; dt2 < 4; dt2++) {
                uint32_t V4[4];
                ldsm_x4t(V4, smem_u32(&Vb[(j2 * 16 + vr) * 72 + dt2 * 16 + vco]));
                mma16816(o[2 * dt2],     Ae, V4);
                mma16816(o[2 * dt2 + 1], Ae, V4 + 2);
            }
        }
        cp_wait0();
        __syncthreads();
    }

    float* obase = out + ((size_t)b * N_ + nr0) * D_;
    const int col0 = (lane & 3) * 2;
    #pragma unroll
    for (int dt = 0; dt < 8; dt++) {
        *(float2*)&obase[dt * 8 + col0]          = make_float2(o[dt][0], o[dt][1]);
        *(float2*)&obase[8 * D_ + dt * 8 + col0] = make_float2(o[dt][2], o[dt][3]);
    }
}

// ---------------------------------------------------------------------------
extern "C" void kernel_launch(void* const* d_in, const int* in_sizes, int n_in,
                              void* d_out, int out_size)
{
    const float* q = (const float*)d_in[0];
    const float* k = (const float*)d_in[1];
    const float* v = (const float*)d_in[2];
    const int* mask = (const int*)d_in[3];
    float* out = (float*)d_out;

    static bool attr_set = false;
    if (!attr_set) {
        cudaFuncSetAttribute(out_kernel, cudaFuncAttributeMaxDynamicSharedMemorySize, 55296);
        attr_set = true;
    }

    pack_mask_kernel<<<(B_ * 64 * 64) / 8, 256>>>(mask);
    convert_qk_kernel<<<(unsigned)(((size_t)B_ * N_ * D_) / 256), 256>>>(q, k);
    colsum_kernel<<<dim3(N_ / 128, B_), 256>>>(v);
    out_kernel<<<dim3(N_ / 128, B_), 256, 55296>>>(out);
}